// round 4
// baseline (speedup 1.0000x reference)
#include <cuda_runtime.h>

// Problem constants
#define B_   32
#define C_   256
#define H_   128
#define W_   128
#define R_   128
#define F_   256
#define HP   126
#define WP   126
#define WPAD 128   // z padded width so GEMM-3 N-tiles are one full row

// Scratch (allocation-free: __device__ globals)
__device__ float g_y[(size_t)B_ * R_ * H_ * W_];     // [b][r][h][w]  268 MB
__device__ float g_z[(size_t)B_ * R_ * HP * WPAD];   // [b][r][p][wpad] 264 MB

// ---- packed f32x2 helpers (sm_103a) -------------------------------------
__device__ __forceinline__ unsigned long long pack_dup(float a) {
    unsigned long long r;
    asm("mov.b64 %0, {%1, %1};" : "=l"(r) : "f"(a));
    return r;
}
__device__ __forceinline__ void ffma2(unsigned long long &d,
                                      unsigned long long a,
                                      unsigned long long b) {
    asm("fma.rn.f32x2 %0, %1, %2, %0;" : "+l"(d) : "l"(a), "l"(b));
}
__device__ __forceinline__ float2 unpack2(unsigned long long v) {
    float2 f;
    asm("mov.b64 {%0, %1}, %2;" : "=f"(f.x), "=f"(f.y) : "l"(v));
    return f;
}

// =========================================================================
// Kernel 1: channel mix   y[b,r,h,w] = sum_c f3[c,r] * x[b,c,h,w]
// GEMM per (b, h-row): M=128 (r), N=128 (w), K=256 (c)
// =========================================================================
__global__ __launch_bounds__(256)
void k1_channel_mix(const float* __restrict__ x, const float* __restrict__ f3) {
    __shared__ float As[2][16][128];   // [k][r]
    __shared__ float Bs[2][16][128];   // [k][w]

    const int b  = blockIdx.y;
    const int h  = blockIdx.x;
    const int tid = threadIdx.x;
    const int tx = tid & 15, ty = tid >> 4;
    const int lk = tid >> 5;            // 0..7
    const int lm = (tid * 4) & 127;     // 0,4,...,124

    const float* Ag = f3;                                           // [256][128]
    const float* Bg = x + ((size_t)b * C_) * (H_ * W_) + (size_t)h * W_;

    unsigned long long acc[8][4];
#pragma unroll
    for (int i = 0; i < 8; ++i)
#pragma unroll
        for (int j = 0; j < 4; ++j) acc[i][j] = 0ULL;

    // preload chunk 0
    {
        float4 a0 = *(const float4*)(Ag + (size_t)(lk)     * R_ + lm);
        float4 a1 = *(const float4*)(Ag + (size_t)(lk + 8) * R_ + lm);
        float4 b0 = *(const float4*)(Bg + (size_t)(lk)     * (H_ * W_) + lm);
        float4 b1 = *(const float4*)(Bg + (size_t)(lk + 8) * (H_ * W_) + lm);
        *(float4*)&As[0][lk][lm]     = a0;
        *(float4*)&As[0][lk + 8][lm] = a1;
        *(float4*)&Bs[0][lk][lm]     = b0;
        *(float4*)&Bs[0][lk + 8][lm] = b1;
    }
    __syncthreads();

    int cur = 0;
#pragma unroll 1
    for (int kc = 0; kc < 16; ++kc) {
        float4 na0, na1, nb0, nb1;
        const bool more = (kc + 1) < 16;
        if (more) {
            int k0 = (kc + 1) * 16;
            na0 = *(const float4*)(Ag + (size_t)(k0 + lk)     * R_ + lm);
            na1 = *(const float4*)(Ag + (size_t)(k0 + lk + 8) * R_ + lm);
            nb0 = *(const float4*)(Bg + (size_t)(k0 + lk)     * (H_ * W_) + lm);
            nb1 = *(const float4*)(Bg + (size_t)(k0 + lk + 8) * (H_ * W_) + lm);
        }
#pragma unroll
        for (int k = 0; k < 16; ++k) {
            float4 a0 = *(const float4*)&As[cur][k][ty * 4];
            float4 a1 = *(const float4*)&As[cur][k][64 + ty * 4];
            ulonglong2 b0 = *(const ulonglong2*)&Bs[cur][k][tx * 4];
            ulonglong2 b1 = *(const ulonglong2*)&Bs[cur][k][64 + tx * 4];
            unsigned long long ap[8];
            ap[0] = pack_dup(a0.x); ap[1] = pack_dup(a0.y);
            ap[2] = pack_dup(a0.z); ap[3] = pack_dup(a0.w);
            ap[4] = pack_dup(a1.x); ap[5] = pack_dup(a1.y);
            ap[6] = pack_dup(a1.z); ap[7] = pack_dup(a1.w);
#pragma unroll
            for (int i = 0; i < 8; ++i) {
                ffma2(acc[i][0], ap[i], b0.x);
                ffma2(acc[i][1], ap[i], b0.y);
                ffma2(acc[i][2], ap[i], b1.x);
                ffma2(acc[i][3], ap[i], b1.y);
            }
        }
        if (more) {
            int nxt = cur ^ 1;
            *(float4*)&As[nxt][lk][lm]     = na0;
            *(float4*)&As[nxt][lk + 8][lm] = na1;
            *(float4*)&Bs[nxt][lk][lm]     = nb0;
            *(float4*)&Bs[nxt][lk + 8][lm] = nb1;
            __syncthreads();
            cur = nxt;
        }
    }

    // store y[b][r][h][w]
    float* yb = g_y + (((size_t)b * R_) * H_ + h) * W_;
#pragma unroll
    for (int i = 0; i < 8; ++i) {
        int r = (i < 4) ? (ty * 4 + i) : (64 + ty * 4 + (i - 4));
        float* row = yb + (size_t)r * (H_ * W_);
        float2 c0 = unpack2(acc[i][0]), c1 = unpack2(acc[i][1]);
        float2 c2 = unpack2(acc[i][2]), c3 = unpack2(acc[i][3]);
        *(float4*)(row + tx * 4)      = make_float4(c0.x, c0.y, c1.x, c1.y);
        *(float4*)(row + 64 + tx * 4) = make_float4(c2.x, c2.y, c3.x, c3.y);
    }
}

// =========================================================================
// Kernel 2: separable depthwise  z[b,r,p,q] = sum_{a,c} y[b,r,p+a,q+c]*f1[a,r]*f2[c,r]
// 4 outputs/thread along q; pads q=126,127 with zeros.
// =========================================================================
__global__ __launch_bounds__(128)
void k2_depthwise(const float* __restrict__ f1, const float* __restrict__ f2) {
    const int tid  = threadIdx.x;      // 128
    const int qg   = tid & 31;         // 0..31
    const int psub = tid >> 5;         // 0..3
    const int p = blockIdx.x * 4 + psub;
    const int r = blockIdx.y;
    const int b = blockIdx.z;
    if (p >= HP) return;

    const float w0 = f2[r],       w1 = f2[128 + r], w2 = f2[256 + r];
    const float v0 = f1[r],       v1 = f1[128 + r], v2 = f1[256 + r];

    const float* yb = g_y + ((((size_t)b * R_) + r) * H_ + p) * W_;
    const int q0 = qg * 4;

    float z0 = 0.f, z1 = 0.f, z2 = 0.f, z3 = 0.f;
#pragma unroll
    for (int a = 0; a < 3; ++a) {
        const float* row = yb + a * W_ + q0;
        float4 t = *(const float4*)row;
        float t4 = 0.f, t5 = 0.f;
        if (q0 + 5 <= 127) {
            float2 u = *(const float2*)(row + 4);
            t4 = u.x; t5 = u.y;
        }
        const float va = (a == 0) ? v0 : ((a == 1) ? v1 : v2);
        float h0 = t.x * w0 + t.y * w1 + t.z * w2;
        float h1 = t.y * w0 + t.z * w1 + t.w * w2;
        float h2 = t.z * w0 + t.w * w1 + t4  * w2;
        float h3 = t.w * w0 + t4  * w1 + t5  * w2;
        z0 += va * h0; z1 += va * h1; z2 += va * h2; z3 += va * h3;
    }
    if (qg == 31) { z2 = 0.f; z3 = 0.f; }   // pad columns 126,127

    float* zp = g_z + ((((size_t)b * R_) + r) * HP + p) * WPAD + q0;
    *(float4*)zp = make_float4(z0, z1, z2, z3);
}

// =========================================================================
// Kernel 3: out[b,f,p,q] = sum_r f0[f,r] * z[b,r,p,q]
// GEMM per (b, m-tile, p-row): M=128 (f), N=128 (q padded), K=128 (r)
// =========================================================================
__global__ __launch_bounds__(256)
void k3_output_gemm(const float* __restrict__ f0, float* __restrict__ out) {
    __shared__ float As[2][16][128];   // [k][f]  (transposed f0)
    __shared__ float Bs[2][16][128];   // [k][q]

    const int b  = blockIdx.z;
    const int m0 = blockIdx.y * 128;
    const int p  = blockIdx.x;          // 0..125
    const int tid = threadIdx.x;
    const int tx = tid & 15, ty = tid >> 4;
    const int am = (tid * 4) >> 4;      // 0..63 (pass 2 adds 64)
    const int ak = (tid * 4) & 15;      // 0,4,8,12
    const int lk = tid >> 5;
    const int lm = (tid * 4) & 127;

    const float* Ag = f0 + (size_t)m0 * R_;                         // [128][128]
    const float* Bg = g_z + (size_t)b * R_ * HP * WPAD + (size_t)p * WPAD;
    const int bstride = HP * WPAD;      // 16128

    unsigned long long acc[8][4];
#pragma unroll
    for (int i = 0; i < 8; ++i)
#pragma unroll
        for (int j = 0; j < 4; ++j) acc[i][j] = 0ULL;

    // preload chunk 0
    {
        float4 v0 = *(const float4*)(Ag + (size_t)am * R_ + ak);
        float4 v1 = *(const float4*)(Ag + (size_t)(am + 64) * R_ + ak);
        As[0][ak + 0][am] = v0.x; As[0][ak + 1][am] = v0.y;
        As[0][ak + 2][am] = v0.z; As[0][ak + 3][am] = v0.w;
        As[0][ak + 0][am + 64] = v1.x; As[0][ak + 1][am + 64] = v1.y;
        As[0][ak + 2][am + 64] = v1.z; As[0][ak + 3][am + 64] = v1.w;
        float4 b0 = *(const float4*)(Bg + (size_t)(lk)     * bstride + lm);
        float4 b1 = *(const float4*)(Bg + (size_t)(lk + 8) * bstride + lm);
        *(float4*)&Bs[0][lk][lm]     = b0;
        *(float4*)&Bs[0][lk + 8][lm] = b1;
    }
    __syncthreads();

    int cur = 0;
#pragma unroll 1
    for (int kc = 0; kc < 8; ++kc) {
        float4 nv0, nv1, nb0, nb1;
        const bool more = (kc + 1) < 8;
        if (more) {
            int k0 = (kc + 1) * 16;
            nv0 = *(const float4*)(Ag + (size_t)am * R_ + k0 + ak);
            nv1 = *(const float4*)(Ag + (size_t)(am + 64) * R_ + k0 + ak);
            nb0 = *(const float4*)(Bg + (size_t)(k0 + lk)     * bstride + lm);
            nb1 = *(const float4*)(Bg + (size_t)(k0 + lk + 8) * bstride + lm);
        }
#pragma unroll
        for (int k = 0; k < 16; ++k) {
            float4 a0 = *(const float4*)&As[cur][k][ty * 4];
            float4 a1 = *(const float4*)&As[cur][k][64 + ty * 4];
            ulonglong2 b0 = *(const ulonglong2*)&Bs[cur][k][tx * 4];
            ulonglong2 b1 = *(const ulonglong2*)&Bs[cur][k][64 + tx * 4];
            unsigned long long ap[8];
            ap[0] = pack_dup(a0.x); ap[1] = pack_dup(a0.y);
            ap[2] = pack_dup(a0.z); ap[3] = pack_dup(a0.w);
            ap[4] = pack_dup(a1.x); ap[5] = pack_dup(a1.y);
            ap[6] = pack_dup(a1.z); ap[7] = pack_dup(a1.w);
#pragma unroll
            for (int i = 0; i < 8; ++i) {
                ffma2(acc[i][0], ap[i], b0.x);
                ffma2(acc[i][1], ap[i], b0.y);
                ffma2(acc[i][2], ap[i], b1.x);
                ffma2(acc[i][3], ap[i], b1.y);
            }
        }
        if (more) {
            int nxt = cur ^ 1;
            As[nxt][ak + 0][am] = nv0.x; As[nxt][ak + 1][am] = nv0.y;
            As[nxt][ak + 2][am] = nv0.z; As[nxt][ak + 3][am] = nv0.w;
            As[nxt][ak + 0][am + 64] = nv1.x; As[nxt][ak + 1][am + 64] = nv1.y;
            As[nxt][ak + 2][am + 64] = nv1.z; As[nxt][ak + 3][am + 64] = nv1.w;
            *(float4*)&Bs[nxt][lk][lm]     = nb0;
            *(float4*)&Bs[nxt][lk + 8][lm] = nb1;
            __syncthreads();
            cur = nxt;
        }
    }

    // store out[b][f][p][q], q < 126  (rows are 126 floats -> only 8B aligned)
#pragma unroll
    for (int i = 0; i < 8; ++i) {
        int fl = (i < 4) ? (ty * 4 + i) : (64 + ty * 4 + (i - 4));
        float* row = out + (((size_t)(b * F_ + m0 + fl)) * HP + p) * WP;
        float2 c0 = unpack2(acc[i][0]), c1 = unpack2(acc[i][1]);
        float2 c2 = unpack2(acc[i][2]), c3 = unpack2(acc[i][3]);
        const int q0 = tx * 4;        // 0..60, always valid
        *(float2*)(row + q0)     = c0;
        *(float2*)(row + q0 + 2) = c1;
        const int q1 = 64 + tx * 4;   // 64..124
        *(float2*)(row + q1) = c2;                     // q1,q1+1 <= 125 always
        if (q1 + 2 < WP) *(float2*)(row + q1 + 2) = c3; // skip q=126,127
    }
}

extern "C" void kernel_launch(void* const* d_in, const int* in_sizes, int n_in,
                              void* d_out, int out_size) {
    const float* x  = (const float*)d_in[0];
    const float* f0 = (const float*)d_in[1];
    const float* f1 = (const float*)d_in[2];
    const float* f2 = (const float*)d_in[3];
    const float* f3 = (const float*)d_in[4];
    float* out = (float*)d_out;

    // K1: per (h-row, batch) GEMM tiles
    k1_channel_mix<<<dim3(H_, B_), 256>>>(x, f3);
    // K2: depthwise 3x3 separable, 4 q-outputs per thread
    k2_depthwise<<<dim3(32, R_, B_), 128>>>(f1, f2);
    // K3: per (p-row, m-tile, batch) GEMM tiles
    k3_output_gemm<<<dim3(HP, F_ / 128, B_), 256>>>(f0, out);
}

// round 6
// speedup vs baseline: 1.9041x; 1.9041x over previous
#include <cuda_runtime.h>
#include <cuda_fp16.h>
#include <cstdint>

#define B_   32
#define C_   256
#define H_   128
#define W_   128
#define R_   128
#define F_   256
#define HP   126
#define WP   126
#define WPAD 128
#define HW_  (H_ * W_)

// ---- device scratch (allocation-free) -----------------------------------
__device__ float  g_y [(size_t)B_ * R_ * H_ * W_];     // fp32 268 MB
__device__ __half g_zh[(size_t)B_ * R_ * HP * WPAD];   // fp16 132 MB
__device__ __half g_f3h[128 * 256], g_f3l[128 * 256];  // f3^T split [r][c]
__device__ __half g_f0h[256 * 128], g_f0l[256 * 128];  // f0 split [f][r]

// ---- warp MMA helpers (baseline PTX, works on plain sm_103) -------------
__device__ __forceinline__ uint32_t smem_u32(const void* p) {
    uint32_t a;
    asm("{ .reg .u64 t; cvta.to.shared.u64 t, %1; cvt.u32.u64 %0, t; }"
        : "=r"(a) : "l"(p));
    return a;
}
__device__ __forceinline__ void ldsm_x4(uint32_t* r, uint32_t addr) {
    asm volatile("ldmatrix.sync.aligned.m8n8.x4.shared.b16 {%0,%1,%2,%3}, [%4];"
                 : "=r"(r[0]), "=r"(r[1]), "=r"(r[2]), "=r"(r[3]) : "r"(addr));
}
__device__ __forceinline__ void ldsm_x4t(uint32_t* r, uint32_t addr) {
    asm volatile("ldmatrix.sync.aligned.m8n8.x4.trans.shared.b16 {%0,%1,%2,%3}, [%4];"
                 : "=r"(r[0]), "=r"(r[1]), "=r"(r[2]), "=r"(r[3]) : "r"(addr));
}
__device__ __forceinline__ void mma16816(float* c, const uint32_t* a,
                                         const uint32_t* b) {
    asm volatile(
        "mma.sync.aligned.m16n8k16.row.col.f32.f16.f16.f32 "
        "{%0,%1,%2,%3}, {%4,%5,%6,%7}, {%8,%9}, {%0,%1,%2,%3};"
        : "+f"(c[0]), "+f"(c[1]), "+f"(c[2]), "+f"(c[3])
        : "r"(a[0]), "r"(a[1]), "r"(a[2]), "r"(a[3]), "r"(b[0]), "r"(b[1]));
}

#define A_LD 24    // halves per A smem row (16 + 8 pad) -> 48B stride
#define B_LD 136   // halves per B smem row (128 + 8 pad) -> 272B stride

// =========================================================================
// Setup: split f0 -> [f][r] hi/lo ; transpose+split f3 -> [r][c] hi/lo
// =========================================================================
__global__ void ksplit_weights(const float* __restrict__ f0,
                               const float* __restrict__ f3) {
    int i = blockIdx.x * 256 + threadIdx.x;     // 0..32767
    if (i < 256 * 128) {
        float v = f0[i];
        __half h = __float2half_rn(v);
        g_f0h[i] = h;
        g_f0l[i] = __float2half_rn(v - __half2float(h));
    }
    if (i < 128 * 256) {
        int m = i >> 8, k = i & 255;            // f3 gmem layout: [c][r]
        float v = f3[k * 128 + m];
        __half h = __float2half_rn(v);
        g_f3h[m * 256 + k] = h;
        g_f3l[m * 256 + k] = __float2half_rn(v - __half2float(h));
    }
}

// =========================================================================
// K1: y[b,r,h,w] = sum_c f3t[r,c] x[b,c,h,w]
// block: M=128 (r), N=128 (w, one h row), K=256 (c), chunks of 16
// warps 4m x 2n, warp tile 32x64, A split hi/lo
// =========================================================================
__global__ __launch_bounds__(256)
void k1_mma(const float* __restrict__ x) {
    __shared__ __half As[2][2][128 * A_LD];     // [stage][split]
    __shared__ __half Bs[2][16 * B_LD];         // [stage][k][n]

    const int tid = threadIdx.x, wid = tid >> 5, lane = tid & 31;
    const int b = blockIdx.y, h = blockIdx.x;
    const int wm = wid & 3, wn = wid >> 2;
    const float* xb = x + ((size_t)b * C_) * HW_ + (size_t)h * W_;

    float acc[2][8][4];
#pragma unroll
    for (int i = 0; i < 2; ++i)
#pragma unroll
        for (int j = 0; j < 8; ++j)
#pragma unroll
            for (int q = 0; q < 4; ++q) acc[i][j][q] = 0.f;

    const int m = tid >> 1, kh = (tid & 1) * 8;

    // preload chunk 0
    {
        *(uint4*)&As[0][0][m * A_LD + kh] = *(const uint4*)&g_f3h[m * 256 + kh];
        *(uint4*)&As[0][1][m * A_LD + kh] = *(const uint4*)&g_f3l[m * 256 + kh];
#pragma unroll
        for (int j = tid; j < 512; j += 256) {
            int k = j >> 5, c4 = (j & 31) * 4;
            float4 v = *(const float4*)(xb + (size_t)k * HW_ + c4);
            __half2 p0 = __floats2half2_rn(v.x, v.y);
            __half2 p1 = __floats2half2_rn(v.z, v.w);
            uint2 w; w.x = *(uint32_t*)&p0; w.y = *(uint32_t*)&p1;
            *(uint2*)&Bs[0][k * B_LD + c4] = w;
        }
    }
    __syncthreads();

    // per-thread ldmatrix address components
    const uint32_t aBase = smem_u32(&As[0][0][0]);
    const uint32_t bBase = smem_u32(&Bs[0][0]);
    const int arow = wm * 32 + (lane & 15);
    const int acol = (lane >> 4) * 8;
    const int brow = (lane & 7) + ((lane >> 3) & 1) * 8;
    const int bcol = wn * 64 + ((lane >> 4) & 1) * 8;

    int cur = 0;
#pragma unroll 1
    for (int kc = 0; kc < 16; ++kc) {
        uint4 pa0, pa1; float4 pb0, pb1;
        const bool more = (kc + 1) < 16;
        if (more) {
            int c0n = (kc + 1) * 16;
            pa0 = *(const uint4*)&g_f3h[m * 256 + c0n + kh];
            pa1 = *(const uint4*)&g_f3l[m * 256 + c0n + kh];
            int k0 = tid >> 5, c40 = (tid & 31) * 4;
            pb0 = *(const float4*)(xb + (size_t)(c0n + k0) * HW_ + c40);
            int j1 = tid + 256, k1 = j1 >> 5, c41 = (j1 & 31) * 4;
            pb1 = *(const float4*)(xb + (size_t)(c0n + k1) * HW_ + c41);
        }

        // ---- compute chunk ----
        uint32_t a[2][2][4];
        const uint32_t aS = aBase + cur * (2 * 128 * A_LD * 2);
#pragma unroll
        for (int sp = 0; sp < 2; ++sp)
#pragma unroll
            for (int mf = 0; mf < 2; ++mf)
                ldsm_x4(a[sp][mf],
                        aS + (sp * 128 * A_LD + (arow + mf * 16) * A_LD + acol) * 2);
        const uint32_t bS = bBase + cur * (16 * B_LD * 2);
#pragma unroll
        for (int g = 0; g < 4; ++g) {
            uint32_t bf[4];
            ldsm_x4t(bf, bS + (brow * B_LD + bcol + g * 16) * 2);
#pragma unroll
            for (int sp = 0; sp < 2; ++sp)
#pragma unroll
                for (int mf = 0; mf < 2; ++mf) {
                    mma16816(acc[mf][g * 2 + 0], a[sp][mf], bf + 0);
                    mma16816(acc[mf][g * 2 + 1], a[sp][mf], bf + 2);
                }
        }

        if (more) {
            int nxt = cur ^ 1;
            *(uint4*)&As[nxt][0][m * A_LD + kh] = pa0;
            *(uint4*)&As[nxt][1][m * A_LD + kh] = pa1;
            {
                int k0 = tid >> 5, c40 = (tid & 31) * 4;
                __half2 p0 = __floats2half2_rn(pb0.x, pb0.y);
                __half2 p1 = __floats2half2_rn(pb0.z, pb0.w);
                uint2 w; w.x = *(uint32_t*)&p0; w.y = *(uint32_t*)&p1;
                *(uint2*)&Bs[nxt][k0 * B_LD + c40] = w;
                int j1 = tid + 256, k1 = j1 >> 5, c41 = (j1 & 31) * 4;
                __half2 q0 = __floats2half2_rn(pb1.x, pb1.y);
                __half2 q1 = __floats2half2_rn(pb1.z, pb1.w);
                uint2 u; u.x = *(uint32_t*)&q0; u.y = *(uint32_t*)&q1;
                *(uint2*)&Bs[nxt][k1 * B_LD + c41] = u;
            }
            __syncthreads();
            cur = nxt;
        }
    }

    // epilogue: y[b][r][h][w]
    const int r0 = wm * 32, n0 = wn * 64;
    const int lr = lane >> 2, lc = (lane & 3) * 2;
#pragma unroll
    for (int mf = 0; mf < 2; ++mf)
#pragma unroll
        for (int g = 0; g < 8; ++g) {
            int r = r0 + mf * 16 + lr;
            int w = n0 + g * 8 + lc;
            float* d0 = g_y + (((size_t)b * R_ + r) * H_ + h) * W_ + w;
            *(float2*)d0 = make_float2(acc[mf][g][0], acc[mf][g][1]);
            float* d1 = g_y + (((size_t)b * R_ + r + 8) * H_ + h) * W_ + w;
            *(float2*)d1 = make_float2(acc[mf][g][2], acc[mf][g][3]);
        }
}

// =========================================================================
// K2: separable depthwise, y fp32 -> z fp16 (padded WPAD, cols 126/127 = 0)
// =========================================================================
__global__ __launch_bounds__(128)
void k2_depthwise(const float* __restrict__ f1, const float* __restrict__ f2) {
    const int tid = threadIdx.x;
    const int qg = tid & 31, psub = tid >> 5;
    const int p = blockIdx.x * 4 + psub;
    const int r = blockIdx.y, b = blockIdx.z;
    if (p >= HP) return;

    const float w0 = f2[r], w1 = f2[128 + r], w2 = f2[256 + r];
    const float v0 = f1[r], v1 = f1[128 + r], v2 = f1[256 + r];

    const float* yb = g_y + ((((size_t)b * R_) + r) * H_ + p) * W_;
    const int q0 = qg * 4;

    float z0 = 0.f, z1 = 0.f, z2 = 0.f, z3 = 0.f;
#pragma unroll
    for (int a = 0; a < 3; ++a) {
        const float* row = yb + a * W_ + q0;
        float4 t = *(const float4*)row;
        float t4 = 0.f, t5 = 0.f;
        if (q0 + 5 <= 127) {
            float2 u = *(const float2*)(row + 4);
            t4 = u.x; t5 = u.y;
        }
        const float va = (a == 0) ? v0 : ((a == 1) ? v1 : v2);
        z0 += va * (t.x * w0 + t.y * w1 + t.z * w2);
        z1 += va * (t.y * w0 + t.z * w1 + t.w * w2);
        z2 += va * (t.z * w0 + t.w * w1 + t4 * w2);
        z3 += va * (t.w * w0 + t4 * w1 + t5 * w2);
    }
    if (qg == 31) { z2 = 0.f; z3 = 0.f; }

    __half2 a2 = __floats2half2_rn(z0, z1);
    __half2 b2 = __floats2half2_rn(z2, z3);
    uint2 w; w.x = *(uint32_t*)&a2; w.y = *(uint32_t*)&b2;
    *(uint2*)(g_zh + ((((size_t)b * R_) + r) * HP + p) * WPAD + q0) = w;
}

// =========================================================================
// K3: out[b,f,p,q] = sum_r f0[f,r] z[b,r,p,q]
// block: M=128 (f half), N=128 (q padded), K=128 (r), chunks of 16
// =========================================================================
__global__ __launch_bounds__(256)
void k3_mma(float* __restrict__ out) {
    __shared__ __half As[2][2][128 * A_LD];
    __shared__ __half Bs[2][16 * B_LD];

    const int tid = threadIdx.x, wid = tid >> 5, lane = tid & 31;
    const int p = blockIdx.x, m0 = blockIdx.y * 128, b = blockIdx.z;
    const int wm = wid & 3, wn = wid >> 2;
    const __half* zb = g_zh + ((size_t)b * R_ * HP + p) * WPAD;
    const size_t zks = (size_t)HP * WPAD;

    float acc[2][8][4];
#pragma unroll
    for (int i = 0; i < 2; ++i)
#pragma unroll
        for (int j = 0; j < 8; ++j)
#pragma unroll
            for (int q = 0; q < 4; ++q) acc[i][j][q] = 0.f;

    const int m = tid >> 1, kh = (tid & 1) * 8;
    const int bk = tid >> 4, bc = (tid & 15) * 8;

    // preload chunk 0
    {
        *(uint4*)&As[0][0][m * A_LD + kh] = *(const uint4*)&g_f0h[(m0 + m) * 128 + kh];
        *(uint4*)&As[0][1][m * A_LD + kh] = *(const uint4*)&g_f0l[(m0 + m) * 128 + kh];
        *(uint4*)&Bs[0][bk * B_LD + bc]   = *(const uint4*)(zb + (size_t)bk * zks + bc);
    }
    __syncthreads();

    const uint32_t aBase = smem_u32(&As[0][0][0]);
    const uint32_t bBase = smem_u32(&Bs[0][0]);
    const int arow = wm * 32 + (lane & 15);
    const int acol = (lane >> 4) * 8;
    const int brow = (lane & 7) + ((lane >> 3) & 1) * 8;
    const int bcol = wn * 64 + ((lane >> 4) & 1) * 8;

    int cur = 0;
#pragma unroll 1
    for (int kc = 0; kc < 8; ++kc) {
        uint4 pa0, pa1, pb;
        const bool more = (kc + 1) < 8;
        if (more) {
            int r0n = (kc + 1) * 16;
            pa0 = *(const uint4*)&g_f0h[(m0 + m) * 128 + r0n + kh];
            pa1 = *(const uint4*)&g_f0l[(m0 + m) * 128 + r0n + kh];
            pb  = *(const uint4*)(zb + (size_t)(r0n + bk) * zks + bc);
        }

        uint32_t a[2][2][4];
        const uint32_t aS = aBase + cur * (2 * 128 * A_LD * 2);
#pragma unroll
        for (int sp = 0; sp < 2; ++sp)
#pragma unroll
            for (int mf = 0; mf < 2; ++mf)
                ldsm_x4(a[sp][mf],
                        aS + (sp * 128 * A_LD + (arow + mf * 16) * A_LD + acol) * 2);
        const uint32_t bS = bBase + cur * (16 * B_LD * 2);
#pragma unroll
        for (int g = 0; g < 4; ++g) {
            uint32_t bf[4];
            ldsm_x4t(bf, bS + (brow * B_LD + bcol + g * 16) * 2);
#pragma unroll
            for (int sp = 0; sp < 2; ++sp)
#pragma unroll
                for (int mf = 0; mf < 2; ++mf) {
                    mma16816(acc[mf][g * 2 + 0], a[sp][mf], bf + 0);
                    mma16816(acc[mf][g * 2 + 1], a[sp][mf], bf + 2);
                }
        }

        if (more) {
            int nxt = cur ^ 1;
            *(uint4*)&As[nxt][0][m * A_LD + kh] = pa0;
            *(uint4*)&As[nxt][1][m * A_LD + kh] = pa1;
            *(uint4*)&Bs[nxt][bk * B_LD + bc]   = pb;
            __syncthreads();
            cur = nxt;
        }
    }

    // epilogue: out[b][f][p][q], skip q >= 126
    const int r0 = wm * 32, n0 = wn * 64;
    const int lr = lane >> 2, lc = (lane & 3) * 2;
#pragma unroll
    for (int mf = 0; mf < 2; ++mf)
#pragma unroll
        for (int g = 0; g < 8; ++g) {
            int f = m0 + r0 + mf * 16 + lr;
            int q = n0 + g * 8 + lc;
            if (q < WP) {
                float* d0 = out + (((size_t)(b * F_ + f)) * HP + p) * WP + q;
                *(float2*)d0 = make_float2(acc[mf][g][0], acc[mf][g][1]);
                float* d1 = out + (((size_t)(b * F_ + f + 8)) * HP + p) * WP + q;
                *(float2*)d1 = make_float2(acc[mf][g][2], acc[mf][g][3]);
            }
        }
}

extern "C" void kernel_launch(void* const* d_in, const int* in_sizes, int n_in,
                              void* d_out, int out_size) {
    const float* x  = (const float*)d_in[0];
    const float* f0 = (const float*)d_in[1];
    const float* f1 = (const float*)d_in[2];
    const float* f2 = (const float*)d_in[3];
    const float* f3 = (const float*)d_in[4];
    float* out = (float*)d_out;

    ksplit_weights<<<128, 256>>>(f0, f3);
    k1_mma<<<dim3(H_, B_), 256>>>(x);
    k2_depthwise<<<dim3(32, R_, B_), 128>>>(f1, f2);
    k3_mma<<<dim3(HP, F_ / 128, B_), 256>>>(out);
}

// round 7
// speedup vs baseline: 2.3646x; 1.2419x over previous
#include <cuda_runtime.h>
#include <cuda_fp16.h>
#include <cstdint>

#define B_   32
#define C_   256
#define H_   128
#define W_   128
#define R_   128
#define F_   256
#define HP   126
#define WP   126
#define WPAD 128
#define HW_  (H_ * W_)

// ---- device scratch (allocation-free) -----------------------------------
__device__ __half g_yh[(size_t)B_ * R_ * H_ * W_];     // fp16 134 MB
__device__ __half g_zh[(size_t)B_ * R_ * HP * WPAD];   // fp16 132 MB
__device__ __half g_f3h[128 * 256];                    // f3^T [r][c]
__device__ __half g_f0h[256 * 128];                    // f0   [f][r]

// ---- PTX helpers --------------------------------------------------------
__device__ __forceinline__ uint32_t smem_u32(const void* p) {
    uint32_t a;
    asm("{ .reg .u64 t; cvta.to.shared.u64 t, %1; cvt.u32.u64 %0, t; }"
        : "=r"(a) : "l"(p));
    return a;
}
__device__ __forceinline__ void ldsm_x4(uint32_t* r, uint32_t addr) {
    asm volatile("ldmatrix.sync.aligned.m8n8.x4.shared.b16 {%0,%1,%2,%3}, [%4];"
                 : "=r"(r[0]), "=r"(r[1]), "=r"(r[2]), "=r"(r[3]) : "r"(addr));
}
__device__ __forceinline__ void ldsm_x4t(uint32_t* r, uint32_t addr) {
    asm volatile("ldmatrix.sync.aligned.m8n8.x4.trans.shared.b16 {%0,%1,%2,%3}, [%4];"
                 : "=r"(r[0]), "=r"(r[1]), "=r"(r[2]), "=r"(r[3]) : "r"(addr));
}
__device__ __forceinline__ void mma16816(float* c, const uint32_t* a,
                                         const uint32_t* b) {
    asm volatile(
        "mma.sync.aligned.m16n8k16.row.col.f32.f16.f16.f32 "
        "{%0,%1,%2,%3}, {%4,%5,%6,%7}, {%8,%9}, {%0,%1,%2,%3};"
        : "+f"(c[0]), "+f"(c[1]), "+f"(c[2]), "+f"(c[3])
        : "r"(a[0]), "r"(a[1]), "r"(a[2]), "r"(a[3]), "r"(b[0]), "r"(b[1]));
}
__device__ __forceinline__ void cp_async16(uint32_t dst, const void* src) {
    asm volatile("{ .reg .u64 g; cvta.to.global.u64 g, %1;"
                 "  cp.async.cg.shared.global [%0], [g], 16; }"
                 :: "r"(dst), "l"(src) : "memory");
}
#define CP_COMMIT() asm volatile("cp.async.commit_group;" ::: "memory")
#define CP_WAIT(n)  asm volatile("cp.async.wait_group %0;" :: "n"(n) : "memory")

#define A_LD 24    // halves per A smem row (16 + 8 pad) -> 48B stride
#define B_LD 136   // halves per B smem row (128 + 8 pad) -> 272B stride

// =========================================================================
// Setup: f0 -> fp16 [f][r] ; f3 transpose -> fp16 [r][c]
// =========================================================================
__global__ void ksplit_weights(const float* __restrict__ f0,
                               const float* __restrict__ f3) {
    int i = blockIdx.x * 256 + threadIdx.x;     // 0..32767
    if (i < 256 * 128) g_f0h[i] = __float2half_rn(f0[i]);
    if (i < 128 * 256) {
        int m = i >> 8, k = i & 255;            // f3 gmem layout: [c][r]
        g_f3h[m * 256 + k] = __float2half_rn(f3[k * 128 + m]);
    }
}

// =========================================================================
// K1: y[b,r,h,w] = sum_c f3t[r,c] x[b,c,h,w]   (y stored fp16)
// block: M=128 (r), N=128 (w, one h row), K=256 (c), chunks of 16
// =========================================================================
__global__ __launch_bounds__(256, 2)
void k1_mma(const float* __restrict__ x) {
    __shared__ __half As[2][128 * A_LD];
    __shared__ __half Bs[2][16 * B_LD];

    const int tid = threadIdx.x, wid = tid >> 5, lane = tid & 31;
    const int b = blockIdx.y, h = blockIdx.x;
    const int wm = wid & 3, wn = wid >> 2;
    const float* xb = x + ((size_t)b * C_) * HW_ + (size_t)h * W_;

    float acc[2][8][4];
#pragma unroll
    for (int i = 0; i < 2; ++i)
#pragma unroll
        for (int j = 0; j < 8; ++j)
#pragma unroll
            for (int q = 0; q < 4; ++q) acc[i][j][q] = 0.f;

    const int m = tid >> 1, kh = (tid & 1) * 8;

    // preload chunk 0
    {
        *(uint4*)&As[0][m * A_LD + kh] = *(const uint4*)&g_f3h[m * 256 + kh];
#pragma unroll
        for (int j = tid; j < 512; j += 256) {
            int k = j >> 5, c4 = (j & 31) * 4;
            float4 v = *(const float4*)(xb + (size_t)k * HW_ + c4);
            __half2 p0 = __floats2half2_rn(v.x, v.y);
            __half2 p1 = __floats2half2_rn(v.z, v.w);
            uint2 w; w.x = *(uint32_t*)&p0; w.y = *(uint32_t*)&p1;
            *(uint2*)&Bs[0][k * B_LD + c4] = w;
        }
    }
    __syncthreads();

    const uint32_t aBase = smem_u32(&As[0][0]);
    const uint32_t bBase = smem_u32(&Bs[0][0]);
    const int arow = wm * 32 + (lane & 15);
    const int acol = (lane >> 4) * 8;
    const int brow = (lane & 7) + ((lane >> 3) & 1) * 8;
    const int bcol = wn * 64 + ((lane >> 4) & 1) * 8;

    int cur = 0;
#pragma unroll 1
    for (int kc = 0; kc < 16; ++kc) {
        uint4 pa0; float4 pb0, pb1;
        const bool more = (kc + 1) < 16;
        if (more) {
            int c0n = (kc + 1) * 16;
            pa0 = *(const uint4*)&g_f3h[m * 256 + c0n + kh];
            int k0 = tid >> 5, c40 = (tid & 31) * 4;
            pb0 = *(const float4*)(xb + (size_t)(c0n + k0) * HW_ + c40);
            int j1 = tid + 256, k1 = j1 >> 5, c41 = (j1 & 31) * 4;
            pb1 = *(const float4*)(xb + (size_t)(c0n + k1) * HW_ + c41);
        }

        uint32_t a[2][4];
        const uint32_t aS = aBase + cur * (128 * A_LD * 2);
#pragma unroll
        for (int mf = 0; mf < 2; ++mf)
            ldsm_x4(a[mf], aS + ((arow + mf * 16) * A_LD + acol) * 2);
        const uint32_t bS = bBase + cur * (16 * B_LD * 2);
#pragma unroll
        for (int g = 0; g < 4; ++g) {
            uint32_t bf[4];
            ldsm_x4t(bf, bS + (brow * B_LD + bcol + g * 16) * 2);
#pragma unroll
            for (int mf = 0; mf < 2; ++mf) {
                mma16816(acc[mf][g * 2 + 0], a[mf], bf + 0);
                mma16816(acc[mf][g * 2 + 1], a[mf], bf + 2);
            }
        }

        if (more) {
            int nxt = cur ^ 1;
            *(uint4*)&As[nxt][m * A_LD + kh] = pa0;
            {
                int k0 = tid >> 5, c40 = (tid & 31) * 4;
                __half2 p0 = __floats2half2_rn(pb0.x, pb0.y);
                __half2 p1 = __floats2half2_rn(pb0.z, pb0.w);
                uint2 w; w.x = *(uint32_t*)&p0; w.y = *(uint32_t*)&p1;
                *(uint2*)&Bs[nxt][k0 * B_LD + c40] = w;
                int j1 = tid + 256, k1 = j1 >> 5, c41 = (j1 & 31) * 4;
                __half2 q0 = __floats2half2_rn(pb1.x, pb1.y);
                __half2 q1 = __floats2half2_rn(pb1.z, pb1.w);
                uint2 u; u.x = *(uint32_t*)&q0; u.y = *(uint32_t*)&q1;
                *(uint2*)&Bs[nxt][k1 * B_LD + c41] = u;
            }
            __syncthreads();
            cur = nxt;
        }
    }

    // epilogue: y fp16
    const int r0 = wm * 32, n0 = wn * 64;
    const int lr = lane >> 2, lc = (lane & 3) * 2;
#pragma unroll
    for (int mf = 0; mf < 2; ++mf)
#pragma unroll
        for (int g = 0; g < 8; ++g) {
            int r = r0 + mf * 16 + lr;
            int w = n0 + g * 8 + lc;
            __half2 v0 = __floats2half2_rn(acc[mf][g][0], acc[mf][g][1]);
            __half2 v1 = __floats2half2_rn(acc[mf][g][2], acc[mf][g][3]);
            *(__half2*)(g_yh + (((size_t)b * R_ + r) * H_ + h) * W_ + w) = v0;
            *(__half2*)(g_yh + (((size_t)b * R_ + r + 8) * H_ + h) * W_ + w) = v1;
        }
}

// =========================================================================
// K2: separable depthwise, y fp16 -> z fp16 (padded WPAD, cols 126/127 = 0)
// =========================================================================
__global__ __launch_bounds__(128)
void k2_depthwise(const float* __restrict__ f1, const float* __restrict__ f2) {
    const int tid = threadIdx.x;
    const int qg = tid & 31, psub = tid >> 5;
    const int p = blockIdx.x * 4 + psub;
    const int r = blockIdx.y, b = blockIdx.z;
    if (p >= HP) return;

    const float w0 = f2[r], w1 = f2[128 + r], w2 = f2[256 + r];
    const float v0 = f1[r], v1 = f1[128 + r], v2 = f1[256 + r];

    const __half* yb = g_yh + ((((size_t)b * R_) + r) * H_ + p) * W_;
    const int q0 = qg * 4;

    float z0 = 0.f, z1 = 0.f, z2 = 0.f, z3 = 0.f;
#pragma unroll
    for (int a = 0; a < 3; ++a) {
        const __half* row = yb + a * W_ + q0;
        __half2 h01 = *(const __half2*)(row);
        __half2 h23 = *(const __half2*)(row + 2);
        float2 t01 = __half22float2(h01);
        float2 t23 = __half22float2(h23);
        float t4 = 0.f, t5 = 0.f;
        if (q0 + 5 <= 127) {
            float2 u = __half22float2(*(const __half2*)(row + 4));
            t4 = u.x; t5 = u.y;
        }
        const float va = (a == 0) ? v0 : ((a == 1) ? v1 : v2);
        z0 += va * (t01.x * w0 + t01.y * w1 + t23.x * w2);
        z1 += va * (t01.y * w0 + t23.x * w1 + t23.y * w2);
        z2 += va * (t23.x * w0 + t23.y * w1 + t4 * w2);
        z3 += va * (t23.y * w0 + t4 * w1 + t5 * w2);
    }
    if (qg == 31) { z2 = 0.f; z3 = 0.f; }

    __half2 a2 = __floats2half2_rn(z0, z1);
    __half2 b2 = __floats2half2_rn(z2, z3);
    uint2 w; w.x = *(uint32_t*)&a2; w.y = *(uint32_t*)&b2;
    *(uint2*)(g_zh + ((((size_t)b * R_) + r) * HP + p) * WPAD + q0) = w;
}

// =========================================================================
// K3: out[b,f,p,q] = sum_r f0[f,r] z[b,r,p,q]
// block: M=128 (f half), N=128 (q padded), K=128, chunks of 16,
// 3-stage cp.async pipeline
// =========================================================================
__global__ __launch_bounds__(256, 2)
void k3_mma(float* __restrict__ out) {
    __shared__ __half As[3][128 * A_LD];
    __shared__ __half Bs[3][16 * B_LD];

    const int tid = threadIdx.x, wid = tid >> 5, lane = tid & 31;
    const int p = blockIdx.x, m0 = blockIdx.y * 128, b = blockIdx.z;
    const int wm = wid & 3, wn = wid >> 2;
    const __half* zb = g_zh + ((size_t)b * R_ * HP + p) * WPAD;
    const size_t zks = (size_t)HP * WPAD;

    float acc[2][8][4];
#pragma unroll
    for (int i = 0; i < 2; ++i)
#pragma unroll
        for (int j = 0; j < 8; ++j)
#pragma unroll
            for (int q = 0; q < 4; ++q) acc[i][j][q] = 0.f;

    // cp.async roles: each thread issues one 16B A seg + one 16B B seg
    const int ar = tid >> 1, asg = (tid & 1) * 8;
    const int br = tid >> 4, bsg = (tid & 15) * 8;

#define K3_ISSUE(kc, st)                                                      \
    do {                                                                      \
        int k0_ = (kc) * 16;                                                  \
        cp_async16(smem_u32(&As[st][ar * A_LD + asg]),                        \
                   g_f0h + (size_t)(m0 + ar) * 128 + k0_ + asg);              \
        cp_async16(smem_u32(&Bs[st][br * B_LD + bsg]),                        \
                   zb + (size_t)(k0_ + br) * zks + bsg);                      \
        CP_COMMIT();                                                          \
    } while (0)

    K3_ISSUE(0, 0);
    K3_ISSUE(1, 1);

    const uint32_t aBase = smem_u32(&As[0][0]);
    const uint32_t bBase = smem_u32(&Bs[0][0]);
    const int arow = wm * 32 + (lane & 15);
    const int acol = (lane >> 4) * 8;
    const int brow = (lane & 7) + ((lane >> 3) & 1) * 8;
    const int bcol = wn * 64 + ((lane >> 4) & 1) * 8;

#pragma unroll 1
    for (int kc = 0; kc < 8; ++kc) {
        if (kc < 7) CP_WAIT(1); else CP_WAIT(0);
        __syncthreads();
        if (kc + 2 < 8) {
            int st = (kc + 2) % 3;
            K3_ISSUE(kc + 2, st);
        }

        const int s = kc % 3;
        uint32_t a[2][4];
        const uint32_t aS = aBase + s * (128 * A_LD * 2);
#pragma unroll
        for (int mf = 0; mf < 2; ++mf)
            ldsm_x4(a[mf], aS + ((arow + mf * 16) * A_LD + acol) * 2);
        const uint32_t bS = bBase + s * (16 * B_LD * 2);
#pragma unroll
        for (int g = 0; g < 4; ++g) {
            uint32_t bf[4];
            ldsm_x4t(bf, bS + (brow * B_LD + bcol + g * 16) * 2);
#pragma unroll
            for (int mf = 0; mf < 2; ++mf) {
                mma16816(acc[mf][g * 2 + 0], a[mf], bf + 0);
                mma16816(acc[mf][g * 2 + 1], a[mf], bf + 2);
            }
        }
    }

    // epilogue: out[b][f][p][q], skip q >= 126
    const int r0 = wm * 32, n0 = wn * 64;
    const int lr = lane >> 2, lc = (lane & 3) * 2;
#pragma unroll
    for (int mf = 0; mf < 2; ++mf)
#pragma unroll
        for (int g = 0; g < 8; ++g) {
            int f = m0 + r0 + mf * 16 + lr;
            int q = n0 + g * 8 + lc;
            if (q < WP) {
                float* d0 = out + (((size_t)(b * F_ + f)) * HP + p) * WP + q;
                *(float2*)d0 = make_float2(acc[mf][g][0], acc[mf][g][1]);
                float* d1 = out + (((size_t)(b * F_ + f + 8)) * HP + p) * WP + q;
                *(float2*)d1 = make_float2(acc[mf][g][2], acc[mf][g][3]);
            }
        }
}

extern "C" void kernel_launch(void* const* d_in, const int* in_sizes, int n_in,
                              void* d_out, int out_size) {
    const float* x  = (const float*)d_in[0];
    const float* f0 = (const float*)d_in[1];
    const float* f1 = (const float*)d_in[2];
    const float* f2 = (const float*)d_in[3];
    const float* f3 = (const float*)d_in[4];
    float* out = (float*)d_out;

    ksplit_weights<<<128, 256>>>(f0, f3);
    k1_mma<<<dim3(H_, B_), 256>>>(x);
    k2_depthwise<<<dim3(32, R_, B_), 128>>>(f1, f2);
    k3_mma<<<dim3(HP, F_ / 128, B_), 256>>>(out);
}